// round 1
// baseline (speedup 1.0000x reference)
#include <cuda_runtime.h>
#include <cuda_bf16.h>

// Scratch accumulator (alloc-free rule: __device__ global).
__device__ double g_spike_acc;

__global__ void zero_acc_kernel() {
    g_spike_acc = 0.0;
}

__global__ void __launch_bounds__(256) spike_loss_kernel(
    const float* __restrict__ outputs,
    const float* __restrict__ target,
    const int* __restrict__ n_steps_p,
    const int* __restrict__ tau_p,
    long long total_elems)
{
    const int   T       = *n_steps_p;
    const float tau     = (float)(*tau_p);
    const float inv_tau = 1.0f / tau;
    const float decay   = 1.0f - inv_tau;
    const long long rows = total_elems / (long long)T;

    const long long tid      = (long long)blockIdx.x * blockDim.x + threadIdx.x;
    const long long nthreads = (long long)gridDim.x * blockDim.x;

    float acc = 0.0f;

    if ((T & 3) == 0) {
        const int T4 = T >> 2;
        for (long long row = tid; row < rows; row += nthreads) {
            const float4* __restrict__ tg = (const float4*)(target  + row * (long long)T);
            const float4* __restrict__ op = (const float4*)(outputs + row * (long long)T);
            float syn = 0.0f;
            #pragma unroll 5
            for (int i = 0; i < T4; ++i) {
                float4 x = tg[i];
                float4 o = op[i];
                float d;
                syn = fmaf(syn, decay, x.x); d = fmaf(-syn, inv_tau, o.x); acc = fmaf(d, d, acc);
                syn = fmaf(syn, decay, x.y); d = fmaf(-syn, inv_tau, o.y); acc = fmaf(d, d, acc);
                syn = fmaf(syn, decay, x.z); d = fmaf(-syn, inv_tau, o.z); acc = fmaf(d, d, acc);
                syn = fmaf(syn, decay, x.w); d = fmaf(-syn, inv_tau, o.w); acc = fmaf(d, d, acc);
            }
        }
    } else {
        for (long long row = tid; row < rows; row += nthreads) {
            const float* __restrict__ tg = target  + row * (long long)T;
            const float* __restrict__ op = outputs + row * (long long)T;
            float syn = 0.0f;
            for (int t = 0; t < T; ++t) {
                syn = fmaf(syn, decay, tg[t]);
                float d = fmaf(-syn, inv_tau, op[t]);
                acc = fmaf(d, d, acc);
            }
        }
    }

    // Warp reduce
    #pragma unroll
    for (int off = 16; off > 0; off >>= 1)
        acc += __shfl_xor_sync(0xFFFFFFFF, acc, off);

    // Block reduce via shared
    __shared__ float warp_sums[8];
    const int wid = threadIdx.x >> 5;
    const int lid = threadIdx.x & 31;
    if (lid == 0) warp_sums[wid] = acc;
    __syncthreads();

    if (wid == 0) {
        float s = (lid < (blockDim.x >> 5)) ? warp_sums[lid] : 0.0f;
        #pragma unroll
        for (int off = 4; off > 0; off >>= 1)
            s += __shfl_xor_sync(0xFFFFFFFF, s, off);
        if (lid == 0)
            atomicAdd(&g_spike_acc, (double)s);
    }
}

__global__ void finalize_kernel(float* out) {
    out[0] = (float)(0.5 * g_spike_acc);
}

extern "C" void kernel_launch(void* const* d_in, const int* in_sizes, int n_in,
                              void* d_out, int out_size)
{
    const float* outputs = (const float*)d_in[0];
    const float* target  = (const float*)d_in[1];
    const int*   n_steps = (const int*)d_in[2];
    const int*   tau_s   = (const int*)d_in[3];
    float*       out     = (float*)d_out;

    const long long total = (long long)in_sizes[0];

    zero_acc_kernel<<<1, 1>>>();
    // 2048 blocks x 256 threads = 524288 threads = one per row for the
    // canonical shape; grid-stride keeps it correct for any T dividing total.
    spike_loss_kernel<<<2048, 256>>>(outputs, target, n_steps, tau_s, total);
    finalize_kernel<<<1, 1>>>(out);
}

// round 3
// speedup vs baseline: 1.0365x; 1.0365x over previous
#include <cuda_runtime.h>
#include <cuda_bf16.h>

#define BLK 256
#define GRID 2048

// Scratch (alloc-free rule: __device__ globals). Zero-initialized once at load;
// g_tick wraps back to 0 every launch via atomicInc, so every call is identical.
__device__ float g_partials[GRID];
__device__ unsigned int g_tick;

__global__ void __launch_bounds__(BLK) spike_loss_kernel(
    const float* __restrict__ outputs,
    const float* __restrict__ target,
    const int* __restrict__ n_steps_p,
    const int* __restrict__ tau_p,
    long long total_elems,
    float* __restrict__ out)
{
    const int   T       = *n_steps_p;
    const float inv_tau = 1.0f / (float)(*tau_p);
    const float decay   = 1.0f - inv_tau;
    const long long rows = total_elems / (long long)T;

    const int lane = threadIdx.x & 31;
    const long long gwarp  = (((long long)blockIdx.x * BLK) + threadIdx.x) >> 5;
    const long long nwarps = ((long long)gridDim.x * BLK) >> 5;

    // decay powers (exact for binary decay; repeated-squaring otherwise)
    const float d2  = decay * decay;
    const float d3  = d2 * decay;
    const float d4  = d2 * d2;
    const float c8  = d4 * d4;
    const float c16 = c8 * c8;
    const float c32 = c16 * c16;
    const float c64 = c32 * c32;
    // decay^(4*lane) by squaring on lane bits (exact products of the above)
    float dp4l = 1.0f;
    {
        float p = d4;
        int lb = lane;
        #pragma unroll
        for (int i = 0; i < 5; ++i) {
            if (lb & 1) dp4l *= p;
            p *= p;
            lb >>= 1;
        }
    }

    float acc = 0.0f;

    for (long long row = gwarp; row < rows; row += nwarps) {
        const float* __restrict__ tg = target  + row * (long long)T;
        const float* __restrict__ op = outputs + row * (long long)T;
        float carry = 0.0f;

        for (int t0 = 0; t0 < T; t0 += 128) {
            const int tb = t0 + (lane << 2);
            float4 x, o;
            if (tb + 3 < T) {
                x = *(const float4*)(tg + tb);
                o = *(const float4*)(op + tb);
            } else {
                x = make_float4(0.f, 0.f, 0.f, 0.f);
                o = make_float4(0.f, 0.f, 0.f, 0.f);
                if (tb     < T) { x.x = tg[tb];     o.x = op[tb];     }
                if (tb + 1 < T) { x.y = tg[tb + 1]; o.y = op[tb + 1]; }
                if (tb + 2 < T) { x.z = tg[tb + 2]; o.z = op[tb + 2]; }
            }

            // local inclusive scan of this lane's 4 elements
            float s0 = x.x;
            float s1 = fmaf(s0, decay, x.y);
            float s2 = fmaf(s1, decay, x.z);
            float s3 = fmaf(s2, decay, x.w);

            // Kogge-Stone inclusive scan across lanes on segment value b
            // (segment multiplier a = decay^4 is lane-uniform -> constant coeffs)
            float b = s3, v;
            v = __shfl_up_sync(0xFFFFFFFF, b, 1);  if (lane >= 1)  b = fmaf(d4,  v, b);
            v = __shfl_up_sync(0xFFFFFFFF, b, 2);  if (lane >= 2)  b = fmaf(c8,  v, b);
            v = __shfl_up_sync(0xFFFFFFFF, b, 4);  if (lane >= 4)  b = fmaf(c16, v, b);
            v = __shfl_up_sync(0xFFFFFFFF, b, 8);  if (lane >= 8)  b = fmaf(c32, v, b);
            v = __shfl_up_sync(0xFFFFFFFF, b, 16); if (lane >= 16) b = fmaf(c64, v, b);

            // exclusive prefix = syn at entry of this lane's segment (chunk-local)
            float P = __shfl_up_sync(0xFFFFFFFF, b, 1);
            if (lane == 0) P = 0.0f;
            // fold in carry from previous chunk (decayed through 4*lane steps)
            const float entering = fmaf(carry, dp4l, P);

            const float y0 = fmaf(entering, decay, s0);
            const float y1 = fmaf(entering, d2,    s1);
            const float y2 = fmaf(entering, d3,    s2);
            const float y3 = fmaf(entering, d4,    s3);

            float e;
            if (tb     < T) { e = fmaf(-y0, inv_tau, o.x); acc = fmaf(e, e, acc); }
            if (tb + 1 < T) { e = fmaf(-y1, inv_tau, o.y); acc = fmaf(e, e, acc); }
            if (tb + 2 < T) { e = fmaf(-y2, inv_tau, o.z); acc = fmaf(e, e, acc); }
            if (tb + 3 < T) { e = fmaf(-y3, inv_tau, o.w); acc = fmaf(e, e, acc); }

            if (t0 + 128 < T)
                carry = __shfl_sync(0xFFFFFFFF, y3, 31);
        }
    }

    // warp reduce (float; per-warp partial is a small sum)
    #pragma unroll
    for (int off = 16; off > 0; off >>= 1)
        acc += __shfl_xor_sync(0xFFFFFFFF, acc, off);

    __shared__ float wsum[BLK / 32];
    const int wid = threadIdx.x >> 5;
    if (lane == 0) wsum[wid] = acc;
    __syncthreads();

    __shared__ bool is_last;
    if (threadIdx.x == 0) {
        float s = 0.0f;
        #pragma unroll
        for (int i = 0; i < BLK / 32; ++i) s += wsum[i];
        g_partials[blockIdx.x] = s;
        __threadfence();
        unsigned prev = atomicInc(&g_tick, gridDim.x - 1);  // wraps to 0 each launch
        is_last = (prev == gridDim.x - 1);
    }
    __syncthreads();

    if (is_last) {
        double d = 0.0;
        for (int i = threadIdx.x; i < (int)gridDim.x; i += BLK)
            d += (double)g_partials[i];
        #pragma unroll
        for (int off = 16; off > 0; off >>= 1)
            d += __shfl_xor_sync(0xFFFFFFFF, d, off);
        __shared__ double dsum[BLK / 32];
        if (lane == 0) dsum[wid] = d;
        __syncthreads();
        if (threadIdx.x == 0) {
            double t = 0.0;
            #pragma unroll
            for (int i = 0; i < BLK / 32; ++i) t += dsum[i];
            out[0] = (float)(0.5 * t);
        }
    }
}

extern "C" void kernel_launch(void* const* d_in, const int* in_sizes, int n_in,
                              void* d_out, int out_size)
{
    const float* outputs = (const float*)d_in[0];
    const float* target  = (const float*)d_in[1];
    const int*   n_steps = (const int*)d_in[2];
    const int*   tau_s   = (const int*)d_in[3];
    float*       out     = (float*)d_out;

    const long long total = (long long)in_sizes[0];

    spike_loss_kernel<<<GRID, BLK>>>(outputs, target, n_steps, tau_s, total, out);
}

// round 4
// speedup vs baseline: 1.1807x; 1.1391x over previous
#include <cuda_runtime.h>
#include <cuda_bf16.h>

#define BLK 256
#define GRID 2048
#define NWARPS ((GRID * BLK) >> 5)

// Scratch (alloc-free rule: __device__ globals). g_tick wraps to 0 every
// launch via atomicInc, so each call is identical (graph-replay safe).
__device__ float g_partials[GRID];
__device__ unsigned int g_tick;

struct ScanCoef {
    float decay, d2, d3, d4, c8, c16, c32, c64, inv_tau;
};

// One row's scan + squared-error accumulation. x/o already loaded (zeros in
// invalid lanes). Guards p0..p3 are loop-invariant predicates.
__device__ __forceinline__ float row_scan(
    float acc, float4 x, float4 o, const ScanCoef& c,
    int lane, bool p0, bool p1, bool p2, bool p3)
{
    // lane-local inclusive scan (4 elements)
    float s0 = x.x;
    float s1 = fmaf(s0, c.decay, x.y);
    float s2 = fmaf(s1, c.decay, x.z);
    float s3 = fmaf(s2, c.decay, x.w);

    // Kogge-Stone across lanes on segment sums (uniform multiplier -> const coeffs)
    float b = s3, v;
    v = __shfl_up_sync(0xFFFFFFFF, b, 1);  if (lane >= 1)  b = fmaf(c.d4,  v, b);
    v = __shfl_up_sync(0xFFFFFFFF, b, 2);  if (lane >= 2)  b = fmaf(c.c8,  v, b);
    v = __shfl_up_sync(0xFFFFFFFF, b, 4);  if (lane >= 4)  b = fmaf(c.c16, v, b);
    v = __shfl_up_sync(0xFFFFFFFF, b, 8);  if (lane >= 8)  b = fmaf(c.c32, v, b);
    v = __shfl_up_sync(0xFFFFFFFF, b, 16); if (lane >= 16) b = fmaf(c.c64, v, b);

    float P = __shfl_up_sync(0xFFFFFFFF, b, 1);
    if (lane == 0) P = 0.0f;

    const float y0 = fmaf(P, c.decay, s0);
    const float y1 = fmaf(P, c.d2,    s1);
    const float y2 = fmaf(P, c.d3,    s2);
    const float y3 = fmaf(P, c.d4,    s3);

    float e;
    if (p0) { e = fmaf(-y0, c.inv_tau, o.x); acc = fmaf(e, e, acc); }
    if (p1) { e = fmaf(-y1, c.inv_tau, o.y); acc = fmaf(e, e, acc); }
    if (p2) { e = fmaf(-y2, c.inv_tau, o.z); acc = fmaf(e, e, acc); }
    if (p3) { e = fmaf(-y3, c.inv_tau, o.w); acc = fmaf(e, e, acc); }
    return acc;
}

__global__ void __launch_bounds__(BLK) spike_loss_kernel(
    const float* __restrict__ outputs,
    const float* __restrict__ target,
    const int* __restrict__ n_steps_p,
    const int* __restrict__ tau_p,
    long long total_elems,
    float* __restrict__ out)
{
    const int T = *n_steps_p;
    ScanCoef c;
    c.inv_tau = 1.0f / (float)(*tau_p);
    c.decay   = 1.0f - c.inv_tau;
    c.d2  = c.decay * c.decay;
    c.d3  = c.d2 * c.decay;
    c.d4  = c.d2 * c.d2;
    c.c8  = c.d4 * c.d4;
    c.c16 = c.c8 * c.c8;
    c.c32 = c.c16 * c.c16;
    c.c64 = c.c32 * c.c32;

    const long long rows = total_elems / (long long)T;
    const int lane  = threadIdx.x & 31;
    const int gwarp = ((blockIdx.x * BLK) + threadIdx.x) >> 5;

    float acc = 0.0f;

    if (T >= 4 && T <= 128) {
        // ---------- fast path: whole row fits one warp chunk ----------
        const int nv = min(max(T - (lane << 2), 0), 4);
        const bool full = (nv == 4);
        const bool p0 = nv > 0, p1 = nv > 1, p2 = nv > 2, p3 = nv > 3;
        const int loff = lane << 2;

        const long long stepT = (long long)NWARPS * T;
        const float* tgp = target  + (long long)gwarp * T + loff;
        const float* opp = outputs + (long long)gwarp * T + loff;

        long long r = gwarp;
        for (; r + NWARPS < rows; r += 2 * NWARPS) {
            float4 x0 = make_float4(0.f,0.f,0.f,0.f), o0 = x0, x1 = x0, o1 = x0;
            if (full) {
                x0 = *(const float4*)tgp;
                o0 = *(const float4*)opp;
                x1 = *(const float4*)(tgp + stepT);
                o1 = *(const float4*)(opp + stepT);
            } else if (p0) {
                x0.x = tgp[0]; o0.x = opp[0];
                x1.x = tgp[stepT]; o1.x = opp[stepT];
                if (p1) { x0.y = tgp[1]; o0.y = opp[1];
                          x1.y = tgp[stepT+1]; o1.y = opp[stepT+1]; }
                if (p2) { x0.z = tgp[2]; o0.z = opp[2];
                          x1.z = tgp[stepT+2]; o1.z = opp[stepT+2]; }
            }
            acc = row_scan(acc, x0, o0, c, lane, p0, p1, p2, p3);
            acc = row_scan(acc, x1, o1, c, lane, p0, p1, p2, p3);
            tgp += 2 * stepT;
            opp += 2 * stepT;
        }
        if (r < rows) {
            float4 x0 = make_float4(0.f,0.f,0.f,0.f), o0 = x0;
            if (full) {
                x0 = *(const float4*)tgp;
                o0 = *(const float4*)opp;
            } else if (p0) {
                x0.x = tgp[0]; o0.x = opp[0];
                if (p1) { x0.y = tgp[1]; o0.y = opp[1]; }
                if (p2) { x0.z = tgp[2]; o0.z = opp[2]; }
            }
            acc = row_scan(acc, x0, o0, c, lane, p0, p1, p2, p3);
        }
    } else {
        // ---------- generic path: chunked scan with carry ----------
        float dp4l = 1.0f;
        {
            float p = c.d4;
            int lb = lane;
            #pragma unroll
            for (int i = 0; i < 5; ++i) {
                if (lb & 1) dp4l *= p;
                p *= p;
                lb >>= 1;
            }
        }
        for (long long row = gwarp; row < rows; row += NWARPS) {
            const float* tg = target  + row * (long long)T;
            const float* op = outputs + row * (long long)T;
            float carry = 0.0f;
            for (int t0 = 0; t0 < T; t0 += 128) {
                const int tb = t0 + (lane << 2);
                float4 x = make_float4(0.f,0.f,0.f,0.f), o = x;
                if (tb + 3 < T) {
                    x = *(const float4*)(tg + tb);
                    o = *(const float4*)(op + tb);
                } else {
                    if (tb     < T) { x.x = tg[tb];   o.x = op[tb];   }
                    if (tb + 1 < T) { x.y = tg[tb+1]; o.y = op[tb+1]; }
                    if (tb + 2 < T) { x.z = tg[tb+2]; o.z = op[tb+2]; }
                }
                float s0 = x.x;
                float s1 = fmaf(s0, c.decay, x.y);
                float s2 = fmaf(s1, c.decay, x.z);
                float s3 = fmaf(s2, c.decay, x.w);
                float b = s3, v;
                v = __shfl_up_sync(0xFFFFFFFF, b, 1);  if (lane >= 1)  b = fmaf(c.d4,  v, b);
                v = __shfl_up_sync(0xFFFFFFFF, b, 2);  if (lane >= 2)  b = fmaf(c.c8,  v, b);
                v = __shfl_up_sync(0xFFFFFFFF, b, 4);  if (lane >= 4)  b = fmaf(c.c16, v, b);
                v = __shfl_up_sync(0xFFFFFFFF, b, 8);  if (lane >= 8)  b = fmaf(c.c32, v, b);
                v = __shfl_up_sync(0xFFFFFFFF, b, 16); if (lane >= 16) b = fmaf(c.c64, v, b);
                float P = __shfl_up_sync(0xFFFFFFFF, b, 1);
                if (lane == 0) P = 0.0f;
                const float entering = fmaf(carry, dp4l, P);
                const float y0 = fmaf(entering, c.decay, s0);
                const float y1 = fmaf(entering, c.d2,    s1);
                const float y2 = fmaf(entering, c.d3,    s2);
                const float y3 = fmaf(entering, c.d4,    s3);
                float e;
                if (tb     < T) { e = fmaf(-y0, c.inv_tau, o.x); acc = fmaf(e, e, acc); }
                if (tb + 1 < T) { e = fmaf(-y1, c.inv_tau, o.y); acc = fmaf(e, e, acc); }
                if (tb + 2 < T) { e = fmaf(-y2, c.inv_tau, o.z); acc = fmaf(e, e, acc); }
                if (tb + 3 < T) { e = fmaf(-y3, c.inv_tau, o.w); acc = fmaf(e, e, acc); }
                if (t0 + 128 < T)
                    carry = __shfl_sync(0xFFFFFFFF, y3, 31);
            }
        }
    }

    // warp reduce
    #pragma unroll
    for (int off = 16; off > 0; off >>= 1)
        acc += __shfl_xor_sync(0xFFFFFFFF, acc, off);

    __shared__ float wsum[BLK / 32];
    const int wid = threadIdx.x >> 5;
    if (lane == 0) wsum[wid] = acc;
    __syncthreads();

    __shared__ bool is_last;
    if (threadIdx.x == 0) {
        float s = 0.0f;
        #pragma unroll
        for (int i = 0; i < BLK / 32; ++i) s += wsum[i];
        g_partials[blockIdx.x] = s;
        __threadfence();
        unsigned prev = atomicInc(&g_tick, GRID - 1);  // wraps to 0 each launch
        is_last = (prev == GRID - 1);
    }
    __syncthreads();

    if (is_last) {
        double d = 0.0;
        for (int i = threadIdx.x; i < GRID; i += BLK)
            d += (double)g_partials[i];
        #pragma unroll
        for (int off = 16; off > 0; off >>= 1)
            d += __shfl_xor_sync(0xFFFFFFFF, d, off);
        __shared__ double dsum[BLK / 32];
        if (lane == 0) dsum[wid] = d;
        __syncthreads();
        if (threadIdx.x == 0) {
            double t = 0.0;
            #pragma unroll
            for (int i = 0; i < BLK / 32; ++i) t += dsum[i];
            out[0] = (float)(0.5 * t);
        }
    }
}

extern "C" void kernel_launch(void* const* d_in, const int* in_sizes, int n_in,
                              void* d_out, int out_size)
{
    const float* outputs = (const float*)d_in[0];
    const float* target  = (const float*)d_in[1];
    const int*   n_steps = (const int*)d_in[2];
    const int*   tau_s   = (const int*)d_in[3];
    float*       out     = (float*)d_out;

    const long long total = (long long)in_sizes[0];

    spike_loss_kernel<<<GRID, BLK>>>(outputs, target, n_steps, tau_s, total, out);
}

// round 6
// speedup vs baseline: 1.2042x; 1.0199x over previous
#include <cuda_runtime.h>
#include <cuda_bf16.h>

#define BLK        128
#define GRID       4096
#define TILE_ROWS  128
#define CHUNK      32                    // time-steps per chunk
#define S4         9                     // float4 row stride in smem (8 + 1 pad, odd -> conflict-free)
#define BUF_F4     (TILE_ROWS * S4)      // 1152 float4 per (buffer, array)
#define OP_OFF     (BUF_F4 * 16)         // byte offset from tg buffer to op buffer
#define SMEM_BYTES (4 * BUF_F4 * 16)     // 2 stages x 2 arrays = 73728 B

// Scratch (alloc-free rule). g_tick wraps to 0 every launch -> graph-replay safe.
__device__ float g_partials[GRID];
__device__ unsigned int g_tick;

__device__ __forceinline__ void cp16(unsigned s, const void* g) {
    asm volatile("cp.async.cg.shared.global [%0], [%1], 16;" :: "r"(s), "l"(g));
}
__device__ __forceinline__ void cp_commit() {
    asm volatile("cp.async.commit_group;");
}
template <int N> __device__ __forceinline__ void cp_wait() {
    asm volatile("cp.async.wait_group %0;" :: "n"(N));
}

__global__ void __launch_bounds__(BLK) spike_loss_kernel(
    const float* __restrict__ outputs,
    const float* __restrict__ target,
    const int* __restrict__ n_steps_p,
    const int* __restrict__ tau_p,
    long long total_elems,
    float* __restrict__ out)
{
    extern __shared__ float4 sm[];

    const int   T       = *n_steps_p;
    const float inv_tau = 1.0f / (float)(*tau_p);
    const float decay   = 1.0f - inv_tau;
    const long long rows = (T > 0) ? total_elems / (long long)T : 0;

    const int tid = threadIdx.x;
    float acc = 0.0f;

    if (T >= 4 && (T & 3) == 0) {
        // ================= fast path: smem transpose, thread-per-row scan =================
        const unsigned sm_base = (unsigned)__cvta_generic_to_shared(sm);
        const int nch   = (T + CHUNK - 1) / CHUNK;
        const int last4 = (T - (nch - 1) * CHUNK) >> 2;   // float4s in last chunk (1..8)

        for (long long tile0 = (long long)blockIdx.x * TILE_ROWS; tile0 < rows;
             tile0 += (long long)GRID * TILE_ROWS) {

            // ---- loader: stage chunk k into stage buffer b (both arrays) ----
            // smem layout: [stage b][tg | op], tg at buffer index 2b, op at 2b+1.
            auto load_chunk = [&](int k, int b) {
                const int t0 = k * CHUNK;
                const int c4 = (k == nch - 1) ? last4 : 8;
                if (c4 == 8) {
                    #pragma unroll
                    for (int it = 0; it < 8 * TILE_ROWS / BLK; ++it) {
                        const int fid = tid + it * BLK;
                        const int r = fid >> 3, j = fid & 7;
                        const long long row = tile0 + r;
                        if (row < rows) {
                            const long long g = row * (long long)T + t0 + 4 * j;
                            const unsigned sa = sm_base + (unsigned)(((b * 2) * BUF_F4 + r * S4 + j) * 16);
                            cp16(sa,          target  + g);
                            cp16(sa + OP_OFF, outputs + g);
                        }
                    }
                } else {
                    for (int fid = tid; fid < TILE_ROWS * c4; fid += BLK) {
                        const int r = fid / c4, j = fid - r * c4;
                        const long long row = tile0 + r;
                        if (row < rows) {
                            const long long g = row * (long long)T + t0 + 4 * j;
                            const unsigned sa = sm_base + (unsigned)(((b * 2) * BUF_F4 + r * S4 + j) * 16);
                            cp16(sa,          target  + g);
                            cp16(sa + OP_OFF, outputs + g);
                        }
                    }
                }
                cp_commit();
            };

            // prologue: prefetch chunks 0 and 1
            load_chunk(0, 0);
            if (nch > 1) load_chunk(1, 1);

            float syn = 0.0f;
            const bool valid = (tile0 + tid) < rows;

            for (int k = 0; k < nch; ++k) {
                if (k + 1 < nch) cp_wait<1>(); else cp_wait<0>();
                __syncthreads();

                const int b  = k & 1;
                const int c4 = (k == nch - 1) ? last4 : 8;
                if (valid) {
                    const float4* xt = sm + (b * 2)     * BUF_F4 + tid * S4;
                    const float4* xo = sm + (b * 2 + 1) * BUF_F4 + tid * S4;
                    if (c4 == 8) {
                        #pragma unroll
                        for (int j = 0; j < 8; ++j) {
                            const float4 x = xt[j];
                            const float4 o = xo[j];
                            float e;
                            syn = fmaf(syn, decay, x.x); e = fmaf(-syn, inv_tau, o.x); acc = fmaf(e, e, acc);
                            syn = fmaf(syn, decay, x.y); e = fmaf(-syn, inv_tau, o.y); acc = fmaf(e, e, acc);
                            syn = fmaf(syn, decay, x.z); e = fmaf(-syn, inv_tau, o.z); acc = fmaf(e, e, acc);
                            syn = fmaf(syn, decay, x.w); e = fmaf(-syn, inv_tau, o.w); acc = fmaf(e, e, acc);
                        }
                    } else {
                        for (int j = 0; j < c4; ++j) {
                            const float4 x = xt[j];
                            const float4 o = xo[j];
                            float e;
                            syn = fmaf(syn, decay, x.x); e = fmaf(-syn, inv_tau, o.x); acc = fmaf(e, e, acc);
                            syn = fmaf(syn, decay, x.y); e = fmaf(-syn, inv_tau, o.y); acc = fmaf(e, e, acc);
                            syn = fmaf(syn, decay, x.z); e = fmaf(-syn, inv_tau, o.z); acc = fmaf(e, e, acc);
                            syn = fmaf(syn, decay, x.w); e = fmaf(-syn, inv_tau, o.w); acc = fmaf(e, e, acc);
                        }
                    }
                }
                __syncthreads();                 // all reads done before buffer reuse
                if (k + 2 < nch) load_chunk(k + 2, b);
            }
        }
    } else if (T > 0) {
        // ================= generic fallback: scalar thread-per-row =================
        const long long gtid = (long long)blockIdx.x * BLK + tid;
        for (long long row = gtid; row < rows; row += (long long)GRID * BLK) {
            const float* tg = target  + row * (long long)T;
            const float* op = outputs + row * (long long)T;
            float syn = 0.0f;
            for (int t = 0; t < T; ++t) {
                syn = fmaf(syn, decay, tg[t]);
                const float e = fmaf(-syn, inv_tau, op[t]);
                acc = fmaf(e, e, acc);
            }
        }
    }

    // ---- block reduce ----
    #pragma unroll
    for (int off = 16; off > 0; off >>= 1)
        acc += __shfl_xor_sync(0xFFFFFFFF, acc, off);

    __shared__ float wsum[BLK / 32];
    const int wid = tid >> 5, lane = tid & 31;
    if (lane == 0) wsum[wid] = acc;
    __syncthreads();

    __shared__ bool is_last;
    if (tid == 0) {
        float s = 0.0f;
        #pragma unroll
        for (int i = 0; i < BLK / 32; ++i) s += wsum[i];
        g_partials[blockIdx.x] = s;
        __threadfence();
        const unsigned prev = atomicInc(&g_tick, GRID - 1);   // wraps to 0 each launch
        is_last = (prev == GRID - 1);
    }
    __syncthreads();

    if (is_last) {
        double d = 0.0;
        for (int i = tid; i < GRID; i += BLK)
            d += (double)g_partials[i];
        #pragma unroll
        for (int off = 16; off > 0; off >>= 1)
            d += __shfl_xor_sync(0xFFFFFFFF, d, off);
        __shared__ double dsum[BLK / 32];
        if (lane == 0) dsum[wid] = d;
        __syncthreads();
        if (tid == 0) {
            double t = 0.0;
            #pragma unroll
            for (int i = 0; i < BLK / 32; ++i) t += dsum[i];
            out[0] = (float)(0.5 * t);
        }
    }
}

extern "C" void kernel_launch(void* const* d_in, const int* in_sizes, int n_in,
                              void* d_out, int out_size)
{
    const float* outputs = (const float*)d_in[0];
    const float* target  = (const float*)d_in[1];
    const int*   n_steps = (const int*)d_in[2];
    const int*   tau_s   = (const int*)d_in[3];
    float*       out     = (float*)d_out;

    const long long total = (long long)in_sizes[0];

    cudaFuncSetAttribute(spike_loss_kernel,
                         cudaFuncAttributeMaxDynamicSharedMemorySize, SMEM_BYTES);
    spike_loss_kernel<<<GRID, BLK, SMEM_BYTES>>>(outputs, target, n_steps, tau_s, total, out);
}

// round 7
// speedup vs baseline: 1.4034x; 1.1654x over previous
#include <cuda_runtime.h>
#include <cuda_bf16.h>

#define BLK        128
#define GRID       456                   // 3 blocks/SM x 152 SMs -> single persistent wave
#define TILE_ROWS  128
#define CHUNK      32                    // time-steps per chunk
#define S4         9                     // float4 row stride in smem (odd -> conflict-free)
#define BUF_F4     (TILE_ROWS * S4)      // 1152 float4 per (slot, array)
#define OP_OFF     (BUF_F4 * 16)         // byte offset tg -> op within a slot
#define SMEM_BYTES (4 * BUF_F4 * 16)     // 2 slots x 2 arrays = 73728 B (3 blocks/SM)

// Scratch (alloc-free rule). g_tick wraps to 0 every launch -> graph-replay safe.
__device__ float g_partials[GRID];
__device__ unsigned int g_tick;

__device__ __forceinline__ void cp16(unsigned s, const void* g) {
    asm volatile("cp.async.cg.shared.global [%0], [%1], 16;" :: "r"(s), "l"(g));
}
__device__ __forceinline__ void cp_commit() {
    asm volatile("cp.async.commit_group;");
}
template <int N> __device__ __forceinline__ void cp_wait() {
    asm volatile("cp.async.wait_group %0;" :: "n"(N));
}

__global__ void __launch_bounds__(BLK) spike_loss_kernel(
    const float* __restrict__ outputs,
    const float* __restrict__ target,
    const int* __restrict__ n_steps_p,
    const int* __restrict__ tau_p,
    long long total_elems,
    float* __restrict__ out)
{
    extern __shared__ float4 sm[];

    const int   T       = *n_steps_p;
    const float inv_tau = 1.0f / (float)(*tau_p);
    const float decay   = 1.0f - inv_tau;
    const long long rows = (T > 0) ? total_elems / (long long)T : 0;

    const int tid = threadIdx.x;
    float acc = 0.0f;

    if (T >= 4 && (T & 3) == 0) {
        // ========== fast path: persistent cross-tile cp.async pipeline ==========
        const unsigned sm_base = (unsigned)__cvta_generic_to_shared(sm);
        const int nch   = (T + CHUNK - 1) / CHUNK;
        const int last4 = (T - (nch - 1) * CHUNK) >> 2;   // float4s in last chunk (1..8)

        const long long tile_base   = (long long)blockIdx.x * TILE_ROWS;
        const long long tile_stride = (long long)GRID * TILE_ROWS;

        // number of tiles this block owns
        long long ntiles = 0;
        if (tile_base < rows)
            ntiles = (rows - tile_base + tile_stride - 1) / tile_stride;
        const long long nci = ntiles * nch;   // flat (tile, chunk) count

        // stage flat-chunk ci into smem slot (both arrays)
        auto load_chunk = [&](long long ci, int slot) {
            const long long tile0 = tile_base + (ci / nch) * tile_stride;
            const int k  = (int)(ci % nch);
            const int t0 = k * CHUNK;
            const int c4 = (k == nch - 1) ? last4 : 8;
            if (c4 == 8) {
                #pragma unroll
                for (int it = 0; it < 8 * TILE_ROWS / BLK; ++it) {
                    const int fid = tid + it * BLK;
                    const int r = fid >> 3, j = fid & 7;
                    const long long row = tile0 + r;
                    if (row < rows) {
                        const long long g = row * (long long)T + t0 + 4 * j;
                        const unsigned sa = sm_base + (unsigned)(((slot * 2) * BUF_F4 + r * S4 + j) * 16);
                        cp16(sa,          target  + g);
                        cp16(sa + OP_OFF, outputs + g);
                    }
                }
            } else {
                for (int fid = tid; fid < TILE_ROWS * c4; fid += BLK) {
                    const int r = fid / c4, j = fid - r * c4;
                    const long long row = tile0 + r;
                    if (row < rows) {
                        const long long g = row * (long long)T + t0 + 4 * j;
                        const unsigned sa = sm_base + (unsigned)(((slot * 2) * BUF_F4 + r * S4 + j) * 16);
                        cp16(sa,          target  + g);
                        cp16(sa + OP_OFF, outputs + g);
                    }
                }
            }
            cp_commit();
        };

        // prologue: one per BLOCK (not per tile)
        if (nci > 0) load_chunk(0, 0);
        if (nci > 1) load_chunk(1, 1);

        float syn = 0.0f;

        for (long long ci = 0; ci < nci; ++ci) {
            if (ci + 1 < nci) cp_wait<1>(); else cp_wait<0>();
            __syncthreads();

            const long long tile0 = tile_base + (ci / nch) * tile_stride;
            const int k    = (int)(ci % nch);
            const int slot = (int)(ci & 1);
            const int c4   = (k == nch - 1) ? last4 : 8;
            if (k == 0) syn = 0.0f;

            if (tile0 + tid < rows) {
                const float4* xt = sm + (slot * 2)     * BUF_F4 + tid * S4;
                const float4* xo = sm + (slot * 2 + 1) * BUF_F4 + tid * S4;
                if (c4 == 8) {
                    #pragma unroll
                    for (int j = 0; j < 8; ++j) {
                        const float4 x = xt[j];
                        const float4 o = xo[j];
                        float e;
                        syn = fmaf(syn, decay, x.x); e = fmaf(-syn, inv_tau, o.x); acc = fmaf(e, e, acc);
                        syn = fmaf(syn, decay, x.y); e = fmaf(-syn, inv_tau, o.y); acc = fmaf(e, e, acc);
                        syn = fmaf(syn, decay, x.z); e = fmaf(-syn, inv_tau, o.z); acc = fmaf(e, e, acc);
                        syn = fmaf(syn, decay, x.w); e = fmaf(-syn, inv_tau, o.w); acc = fmaf(e, e, acc);
                    }
                } else {
                    for (int j = 0; j < c4; ++j) {
                        const float4 x = xt[j];
                        const float4 o = xo[j];
                        float e;
                        syn = fmaf(syn, decay, x.x); e = fmaf(-syn, inv_tau, o.x); acc = fmaf(e, e, acc);
                        syn = fmaf(syn, decay, x.y); e = fmaf(-syn, inv_tau, o.y); acc = fmaf(e, e, acc);
                        syn = fmaf(syn, decay, x.z); e = fmaf(-syn, inv_tau, o.z); acc = fmaf(e, e, acc);
                        syn = fmaf(syn, decay, x.w); e = fmaf(-syn, inv_tau, o.w); acc = fmaf(e, e, acc);
                    }
                }
            }
            __syncthreads();                       // all reads done before slot reuse
            if (ci + 2 < nci) load_chunk(ci + 2, slot);
        }
    } else if (T > 0) {
        // ========== generic fallback: scalar thread-per-row ==========
        const long long gtid = (long long)blockIdx.x * BLK + tid;
        for (long long row = gtid; row < rows; row += (long long)GRID * BLK) {
            const float* tg = target  + row * (long long)T;
            const float* op = outputs + row * (long long)T;
            float syn = 0.0f;
            for (int t = 0; t < T; ++t) {
                syn = fmaf(syn, decay, tg[t]);
                const float e = fmaf(-syn, inv_tau, op[t]);
                acc = fmaf(e, e, acc);
            }
        }
    }

    // ---- block reduce ----
    #pragma unroll
    for (int off = 16; off > 0; off >>= 1)
        acc += __shfl_xor_sync(0xFFFFFFFF, acc, off);

    __shared__ float wsum[BLK / 32];
    const int wid = tid >> 5, lane = tid & 31;
    if (lane == 0) wsum[wid] = acc;
    __syncthreads();

    __shared__ bool is_last;
    if (tid == 0) {
        float s = 0.0f;
        #pragma unroll
        for (int i = 0; i < BLK / 32; ++i) s += wsum[i];
        g_partials[blockIdx.x] = s;
        __threadfence();
        const unsigned prev = atomicInc(&g_tick, GRID - 1);   // wraps to 0 each launch
        is_last = (prev == GRID - 1);
    }
    __syncthreads();

    if (is_last) {
        double d = 0.0;
        for (int i = tid; i < GRID; i += BLK)
            d += (double)g_partials[i];
        #pragma unroll
        for (int off = 16; off > 0; off >>= 1)
            d += __shfl_xor_sync(0xFFFFFFFF, d, off);
        __shared__ double dsum[BLK / 32];
        if (lane == 0) dsum[wid] = d;
        __syncthreads();
        if (tid == 0) {
            double t = 0.0;
            #pragma unroll
            for (int i = 0; i < BLK / 32; ++i) t += dsum[i];
            out[0] = (float)(0.5 * t);
        }
    }
}

extern "C" void kernel_launch(void* const* d_in, const int* in_sizes, int n_in,
                              void* d_out, int out_size)
{
    const float* outputs = (const float*)d_in[0];
    const float* target  = (const float*)d_in[1];
    const int*   n_steps = (const int*)d_in[2];
    const int*   tau_s   = (const int*)d_in[3];
    float*       out     = (float*)d_out;

    const long long total = (long long)in_sizes[0];

    cudaFuncSetAttribute(spike_loss_kernel,
                         cudaFuncAttributeMaxDynamicSharedMemorySize, SMEM_BYTES);
    spike_loss_kernel<<<GRID, BLK, SMEM_BYTES>>>(outputs, target, n_steps, tau_s, total, out);
}

// round 8
// speedup vs baseline: 1.4481x; 1.0319x over previous
#include <cuda_runtime.h>
#include <cuda_bf16.h>

#define BLK        128
#define GRID       456                   // 3 blocks/SM x 152 SMs -> single persistent wave
#define TILE_ROWS  128
#define WROWS      32                    // rows per warp
#define CHUNK      32                    // time-steps per chunk
#define S4         9                     // float4 row stride in smem (odd -> conflict-free)
#define WBUF_F4    (WROWS * S4)          // 288 float4 per (slot, array, warp)
#define SMEM_BYTES (2 * 2 * 4 * WBUF_F4 * 16)   // slots x arrays x warps = 73728 B

// Scratch (alloc-free rule). g_tick wraps to 0 every launch -> graph-replay safe.
__device__ float g_partials[GRID];
__device__ unsigned int g_tick;

__device__ __forceinline__ void cp16(unsigned s, const void* g) {
    asm volatile("cp.async.cg.shared.global [%0], [%1], 16;" :: "r"(s), "l"(g));
}
__device__ __forceinline__ void cp_commit() {
    asm volatile("cp.async.commit_group;");
}
template <int N> __device__ __forceinline__ void cp_wait() {
    asm volatile("cp.async.wait_group %0;" :: "n"(N));
}

__global__ void __launch_bounds__(BLK) spike_loss_kernel(
    const float* __restrict__ outputs,
    const float* __restrict__ target,
    const int* __restrict__ n_steps_p,
    const int* __restrict__ tau_p,
    long long total_elems,
    float* __restrict__ out)
{
    extern __shared__ float4 sm[];

    const int   T       = *n_steps_p;
    const float inv_tau = 1.0f / (float)(*tau_p);
    const float decay   = 1.0f - inv_tau;
    const long long rows = (T > 0) ? total_elems / (long long)T : 0;

    const int tid  = threadIdx.x;
    const int wid  = tid >> 5;
    const int lane = tid & 31;
    float acc = 0.0f;

    if (T >= 4 && (T & 3) == 0) {
        // ===== fast path: per-warp private 2-slot cp.async pipeline, no block barriers =====
        const unsigned sm_base = (unsigned)__cvta_generic_to_shared(sm);
        const int nch   = (T + CHUNK - 1) / CHUNK;
        const int last4 = (T - (nch - 1) * CHUNK) >> 2;   // float4s in last chunk (1..8)

        // this warp's base row within a tile
        const long long wrow_base   = (long long)blockIdx.x * TILE_ROWS + wid * WROWS;
        const long long tile_stride = (long long)GRID * TILE_ROWS;

        long long ntiles = 0;
        {
            const long long first = (long long)blockIdx.x * TILE_ROWS;
            if (first < rows)
                ntiles = (rows - first + tile_stride - 1) / tile_stride;
        }
        const long long nci = ntiles * nch;

        // smem buffer index for (slot, arr) of this warp, in float4 units
        // layout: ((slot*2 + arr)*4 + wid) * WBUF_F4
        auto buf_f4 = [&](int slot, int arr) -> unsigned {
            return (unsigned)(((slot * 2 + arr) * 4 + wid) * WBUF_F4);
        };

        // stage flat-chunk ci into this warp's slot (both arrays)
        auto load_chunk = [&](long long ci, int slot) {
            const long long row0 = wrow_base + (ci / nch) * tile_stride;
            const int k  = (int)(ci % nch);
            const int t0 = k * CHUNK;
            const int c4 = (k == nch - 1) ? last4 : 8;
            const unsigned st = sm_base + buf_f4(slot, 0) * 16;
            const unsigned so = sm_base + buf_f4(slot, 1) * 16;
            if (c4 == 8) {
                #pragma unroll
                for (int it = 0; it < 8; ++it) {           // 32 rows x 8 f4 / 32 lanes
                    const int fid = it * 32 + lane;
                    const int r = fid >> 3, j = fid & 7;
                    const long long row = row0 + r;
                    if (row < rows) {
                        const long long g = row * (long long)T + t0 + 4 * j;
                        const unsigned off = (unsigned)((r * S4 + j) * 16);
                        cp16(st + off, target  + g);
                        cp16(so + off, outputs + g);
                    }
                }
            } else {
                for (int fid = lane; fid < WROWS * c4; fid += 32) {
                    const int r = fid / c4, j = fid - r * c4;
                    const long long row = row0 + r;
                    if (row < rows) {
                        const long long g = row * (long long)T + t0 + 4 * j;
                        const unsigned off = (unsigned)((r * S4 + j) * 16);
                        cp16(st + off, target  + g);
                        cp16(so + off, outputs + g);
                    }
                }
            }
            cp_commit();
        };

        // prologue (per warp)
        if (nci > 0) load_chunk(0, 0);
        if (nci > 1) load_chunk(1, 1);

        float syn = 0.0f;

        for (long long ci = 0; ci < nci; ++ci) {
            if (ci + 1 < nci) cp_wait<1>(); else cp_wait<0>();
            __syncwarp();                          // cross-lane visibility of this warp's loads

            const long long row0 = wrow_base + (ci / nch) * tile_stride;
            const int k    = (int)(ci % nch);
            const int slot = (int)(ci & 1);
            const int c4   = (k == nch - 1) ? last4 : 8;
            if (k == 0) syn = 0.0f;

            if (row0 + lane < rows) {
                const float4* xt = sm + buf_f4(slot, 0) + lane * S4;
                const float4* xo = sm + buf_f4(slot, 1) + lane * S4;
                if (c4 == 8) {
                    #pragma unroll
                    for (int j = 0; j < 8; ++j) {
                        const float4 x = xt[j];
                        const float4 o = xo[j];
                        float e;
                        syn = fmaf(syn, decay, x.x); e = fmaf(-syn, inv_tau, o.x); acc = fmaf(e, e, acc);
                        syn = fmaf(syn, decay, x.y); e = fmaf(-syn, inv_tau, o.y); acc = fmaf(e, e, acc);
                        syn = fmaf(syn, decay, x.z); e = fmaf(-syn, inv_tau, o.z); acc = fmaf(e, e, acc);
                        syn = fmaf(syn, decay, x.w); e = fmaf(-syn, inv_tau, o.w); acc = fmaf(e, e, acc);
                    }
                } else {
                    for (int j = 0; j < c4; ++j) {
                        const float4 x = xt[j];
                        const float4 o = xo[j];
                        float e;
                        syn = fmaf(syn, decay, x.x); e = fmaf(-syn, inv_tau, o.x); acc = fmaf(e, e, acc);
                        syn = fmaf(syn, decay, x.y); e = fmaf(-syn, inv_tau, o.y); acc = fmaf(e, e, acc);
                        syn = fmaf(syn, decay, x.z); e = fmaf(-syn, inv_tau, o.z); acc = fmaf(e, e, acc);
                        syn = fmaf(syn, decay, x.w); e = fmaf(-syn, inv_tau, o.w); acc = fmaf(e, e, acc);
                    }
                }
            }
            __syncwarp();                          // all lanes done reading slot before reuse
            if (ci + 2 < nci) load_chunk(ci + 2, slot);
        }
    } else if (T > 0) {
        // ===== generic fallback: scalar thread-per-row =====
        const long long gtid = (long long)blockIdx.x * BLK + tid;
        for (long long row = gtid; row < rows; row += (long long)GRID * BLK) {
            const float* tg = target  + row * (long long)T;
            const float* op = outputs + row * (long long)T;
            float syn = 0.0f;
            for (int t = 0; t < T; ++t) {
                syn = fmaf(syn, decay, tg[t]);
                const float e = fmaf(-syn, inv_tau, op[t]);
                acc = fmaf(e, e, acc);
            }
        }
    }

    // ---- block reduce ----
    #pragma unroll
    for (int off = 16; off > 0; off >>= 1)
        acc += __shfl_xor_sync(0xFFFFFFFF, acc, off);

    __shared__ float wsum[BLK / 32];
    if (lane == 0) wsum[wid] = acc;
    __syncthreads();

    __shared__ bool is_last;
    if (tid == 0) {
        float s = 0.0f;
        #pragma unroll
        for (int i = 0; i < BLK / 32; ++i) s += wsum[i];
        g_partials[blockIdx.x] = s;
        __threadfence();
        const unsigned prev = atomicInc(&g_tick, GRID - 1);   // wraps to 0 each launch
        is_last = (prev == GRID - 1);
    }
    __syncthreads();

    if (is_last) {
        double d = 0.0;
        for (int i = tid; i < GRID; i += BLK)
            d += (double)g_partials[i];
        #pragma unroll
        for (int off = 16; off > 0; off >>= 1)
            d += __shfl_xor_sync(0xFFFFFFFF, d, off);
        __shared__ double dsum[BLK / 32];
        if (lane == 0) dsum[wid] = d;
        __syncthreads();
        if (tid == 0) {
            double t = 0.0;
            #pragma unroll
            for (int i = 0; i < BLK / 32; ++i) t += dsum[i];
            out[0] = (float)(0.5 * t);
        }
    }
}

extern "C" void kernel_launch(void* const* d_in, const int* in_sizes, int n_in,
                              void* d_out, int out_size)
{
    const float* outputs = (const float*)d_in[0];
    const float* target  = (const float*)d_in[1];
    const int*   n_steps = (const int*)d_in[2];
    const int*   tau_s   = (const int*)d_in[3];
    float*       out     = (float*)d_out;

    const long long total = (long long)in_sizes[0];

    cudaFuncSetAttribute(spike_loss_kernel,
                         cudaFuncAttributeMaxDynamicSharedMemorySize, SMEM_BYTES);
    spike_loss_kernel<<<GRID, BLK, SMEM_BYTES>>>(outputs, target, n_steps, tau_s, total, out);
}